// round 1
// baseline (speedup 1.0000x reference)
#include <cuda_runtime.h>
#include <math.h>

#define S_SEQ 2048
#define NB 64
#define NH 512
#define NF 512
#define NGATE 4
#define NCTA 128
#define REC_THREADS 256

// Scratch: pre-activations xpre[s][gate][b][h]  (1.07 GB), h ping-pong, barriers.
__device__ float    g_xpre[(size_t)S_SEQ * NGATE * NB * NH];
__device__ float    g_hbuf[2][NB * NH];
__device__ unsigned g_bar[S_SEQ];

// -------------------------------------------------------------------------
// Barrier-counter reset (runs before the persistent kernel every launch)
// -------------------------------------------------------------------------
__global__ void reset_kernel() {
    int i = blockIdx.x * blockDim.x + threadIdx.x;
    if (i < S_SEQ) g_bar[i] = 0u;
}

// -------------------------------------------------------------------------
// Input projection: C[r, n] = x[r, :] @ W_g[:, h] + bx[g][h] + bh[g][h]
//   r = b*2048 + s  (rows of x flattened),  n = g*512 + h
// Tiled SGEMM: BM=128, BN=128, BK=16, 256 threads, 8x8 micro-tile (4+4 split)
// -------------------------------------------------------------------------
struct ProjPtrs {
    const float* w[4];
    const float* bx[4];
    const float* bh[4];
};

__global__ __launch_bounds__(256, 2)
void proj_kernel(const float* __restrict__ x, ProjPtrs p) {
    __shared__ float As[16][128];   // transposed A tile: As[k][row]
    __shared__ float Bs[16][128];   // Bs[k][col]

    const int tid   = threadIdx.x;
    const int nTile = blockIdx.x;       // 0..15
    const int mTile = blockIdx.y;       // 0..1023
    const int r0    = mTile * 128;
    const int g     = nTile >> 2;       // 4 tiles of 128 per gate
    const int hc0   = (nTile & 3) * 128;
    const float* W  = p.w[g];

    const int aRow = tid >> 2;          // 0..63
    const int aK4  = tid & 3;           // 0..3
    const int bRow = tid >> 5;          // 0..7
    const int bC4  = tid & 31;          // 0..31

    const int ty = tid >> 4;            // 0..15
    const int tx = tid & 15;            // 0..15

    float4 gA0, gA1, gB0, gB1;

    // prologue load (k0 = 0)
    {
        const float* abase = x + (size_t)(r0 + aRow) * NF + aK4 * 4;
        gA0 = *reinterpret_cast<const float4*>(abase);
        gA1 = *reinterpret_cast<const float4*>(abase + (size_t)64 * NF);
        const float* bbase = W + (size_t)bRow * NH + hc0 + bC4 * 4;
        gB0 = *reinterpret_cast<const float4*>(bbase);
        gB1 = *reinterpret_cast<const float4*>(bbase + (size_t)8 * NH);
    }

    float acc[8][8];
#pragma unroll
    for (int i = 0; i < 8; ++i)
#pragma unroll
        for (int j = 0; j < 8; ++j) acc[i][j] = 0.f;

    for (int it = 0; it < NF / 16; ++it) {
        __syncthreads();
        // deposit current tile into smem (A transposed)
        As[aK4 * 4 + 0][aRow]      = gA0.x;
        As[aK4 * 4 + 1][aRow]      = gA0.y;
        As[aK4 * 4 + 2][aRow]      = gA0.z;
        As[aK4 * 4 + 3][aRow]      = gA0.w;
        As[aK4 * 4 + 0][aRow + 64] = gA1.x;
        As[aK4 * 4 + 1][aRow + 64] = gA1.y;
        As[aK4 * 4 + 2][aRow + 64] = gA1.z;
        As[aK4 * 4 + 3][aRow + 64] = gA1.w;
        *reinterpret_cast<float4*>(&Bs[bRow][bC4 * 4])     = gB0;
        *reinterpret_cast<float4*>(&Bs[bRow + 8][bC4 * 4]) = gB1;
        __syncthreads();

        // prefetch next tile
        if (it + 1 < NF / 16) {
            const int k0 = (it + 1) * 16;
            const float* abase = x + (size_t)(r0 + aRow) * NF + k0 + aK4 * 4;
            gA0 = *reinterpret_cast<const float4*>(abase);
            gA1 = *reinterpret_cast<const float4*>(abase + (size_t)64 * NF);
            const float* bbase = W + (size_t)(k0 + bRow) * NH + hc0 + bC4 * 4;
            gB0 = *reinterpret_cast<const float4*>(bbase);
            gB1 = *reinterpret_cast<const float4*>(bbase + (size_t)8 * NH);
        }

        // compute current tile
#pragma unroll
        for (int kk = 0; kk < 16; ++kk) {
            float4 a0 = *reinterpret_cast<const float4*>(&As[kk][ty * 4]);
            float4 a1 = *reinterpret_cast<const float4*>(&As[kk][64 + ty * 4]);
            float4 b0 = *reinterpret_cast<const float4*>(&Bs[kk][tx * 4]);
            float4 b1 = *reinterpret_cast<const float4*>(&Bs[kk][64 + tx * 4]);
            float av[8] = {a0.x, a0.y, a0.z, a0.w, a1.x, a1.y, a1.z, a1.w};
            float bv[8] = {b0.x, b0.y, b0.z, b0.w, b1.x, b1.y, b1.z, b1.w};
#pragma unroll
            for (int i = 0; i < 8; ++i)
#pragma unroll
                for (int jcol = 0; jcol < 8; ++jcol)
                    acc[i][jcol] += av[i] * bv[jcol];
        }
    }

    // epilogue: add (bx + bh) and store to g_xpre[s][g][b][h]
    const float* bxp = p.bx[g] + hc0 + tx * 4;
    const float* bhp = p.bh[g] + hc0 + tx * 4;
    float4 bxl = *reinterpret_cast<const float4*>(bxp);
    float4 bhl = *reinterpret_cast<const float4*>(bhp);
    float4 bxh = *reinterpret_cast<const float4*>(bxp + 64);
    float4 bhh = *reinterpret_cast<const float4*>(bhp + 64);
    float4 biasLo = make_float4(bxl.x + bhl.x, bxl.y + bhl.y, bxl.z + bhl.z, bxl.w + bhl.w);
    float4 biasHi = make_float4(bxh.x + bhh.x, bxh.y + bhh.y, bxh.z + bhh.z, bxh.w + bhh.w);

#pragma unroll
    for (int rh = 0; rh < 2; ++rh) {
#pragma unroll
        for (int ii = 0; ii < 4; ++ii) {
            const int r  = r0 + rh * 64 + ty * 4 + ii;
            const int bb = r >> 11;          // batch
            const int s  = r & 2047;         // timestep
            const size_t base = ((size_t)(s * 4 + g) * NB + bb) * NH + hc0;
            const int ai = rh * 4 + ii;
            float4 v0 = make_float4(acc[ai][0] + biasLo.x, acc[ai][1] + biasLo.y,
                                    acc[ai][2] + biasLo.z, acc[ai][3] + biasLo.w);
            float4 v1 = make_float4(acc[ai][4] + biasHi.x, acc[ai][5] + biasHi.y,
                                    acc[ai][6] + biasHi.z, acc[ai][7] + biasHi.w);
            *reinterpret_cast<float4*>(&g_xpre[base + tx * 4])      = v0;
            *reinterpret_cast<float4*>(&g_xpre[base + 64 + tx * 4]) = v1;
        }
    }
}

// -------------------------------------------------------------------------
// Persistent recurrent kernel: 128 CTAs, each owns 4 hidden columns (all
// gates, all batches). W_h slice lives in smem for the whole scan; h is
// broadcast through L2 each step (ldcg: L1 is stale across the ping-pong).
// Global barrier per step via pre-zeroed per-step counters.
// -------------------------------------------------------------------------
#define WS_FLOATS (512 * 16)       // w_s[k][jj][g]
#define HS_STRIDE 516              // padded h row (floats)
#define HS_FLOATS (NB * HS_STRIDE)
#define XS_FLOATS (NGATE * NB * 4)
#define REC_SMEM_BYTES ((WS_FLOATS + HS_FLOATS + XS_FLOATS) * 4)

__device__ __forceinline__ float sigmoidf_(float v) {
    return 1.f / (1.f + expf(-v));
}

__global__ __launch_bounds__(REC_THREADS, 1)
void rec_kernel(const float* __restrict__ w_hi, const float* __restrict__ w_hf,
                const float* __restrict__ w_hg, const float* __restrict__ w_ho,
                float* __restrict__ out) {
    extern __shared__ float sm[];
    float* w_s = sm;                       // [k*16 + jj*4 + g]
    float* h_s = sm + WS_FLOATS;           // [b*516 + k]
    float* x_s = h_s + HS_FLOATS;          // [(g*64+b)*4 + jj]

    const int tid = threadIdx.x;
    const int b   = tid & 63;
    const int jj  = tid >> 6;              // 0..3
    const int j0  = blockIdx.x * 4;
    const int j   = j0 + jj;

    // preload this CTA's W_h slice (constant over the whole scan)
    {
        const float* wh[4] = {w_hi, w_hf, w_hg, w_ho};
        for (int idx = tid; idx < WS_FLOATS; idx += REC_THREADS) {
            const int k  = idx >> 4;
            const int jw = (idx >> 2) & 3;
            const int gw = idx & 3;
            w_s[idx] = wh[gw][(size_t)k * NH + j0 + jw];
        }
    }

    const float4* ws4  = reinterpret_cast<const float4*>(w_s) + jj;
    float4*       hs4w = reinterpret_cast<float4*>(h_s);
    const int gl = tid >> 6;   // gate for x staging
    const int bl = tid & 63;

    float creg = 0.f;

    for (int t = 0; t < S_SEQ; ++t) {
        // stage x_t slice (coalesced float4 per thread)
        const float4 xv = *reinterpret_cast<const float4*>(
            &g_xpre[(((size_t)t * 4 + gl) * NB + bl) * NH + j0]);

        // stage full h into smem (L2-coherent loads; skip at t=0 where h=0)
        if (t > 0) {
            const float4* hsrc = reinterpret_cast<const float4*>(g_hbuf[t & 1]);
#pragma unroll 4
            for (int i = tid; i < (NB * NH / 4); i += REC_THREADS) {
                float4 v = __ldcg(hsrc + i);
                const int bb = i >> 7;       // batch row
                const int k4 = i & 127;      // float4 index within row
                hs4w[bb * (HS_STRIDE / 4) + k4] = v;
            }
        }
        *reinterpret_cast<float4*>(&x_s[(gl * NB + bl) * 4]) = xv;
        __syncthreads();

        float a0 = x_s[(0 * NB + b) * 4 + jj];
        float a1 = x_s[(1 * NB + b) * 4 + jj];
        float a2 = x_s[(2 * NB + b) * 4 + jj];
        float a3 = x_s[(3 * NB + b) * 4 + jj];

        if (t > 0) {
            const float4* hrow = reinterpret_cast<const float4*>(h_s) + b * (HS_STRIDE / 4);
#pragma unroll 2
            for (int k4 = 0; k4 < NH / 4; ++k4) {
                const float4 h4 = hrow[k4];
                const float4 w0 = ws4[k4 * 16 + 0];
                a0 += h4.x * w0.x; a1 += h4.x * w0.y; a2 += h4.x * w0.z; a3 += h4.x * w0.w;
                const float4 w1 = ws4[k4 * 16 + 4];
                a0 += h4.y * w1.x; a1 += h4.y * w1.y; a2 += h4.y * w1.z; a3 += h4.y * w1.w;
                const float4 w2 = ws4[k4 * 16 + 8];
                a0 += h4.z * w2.x; a1 += h4.z * w2.y; a2 += h4.z * w2.z; a3 += h4.z * w2.w;
                const float4 w3 = ws4[k4 * 16 + 12];
                a0 += h4.w * w3.x; a1 += h4.w * w3.y; a2 += h4.w * w3.z; a3 += h4.w * w3.w;
            }
        }

        const float ig = sigmoidf_(a0);
        const float fg = sigmoidf_(a1);
        const float gg = tanhf(a2);
        const float og = sigmoidf_(a3);
        creg = fg * creg + ig * gg;
        const float hnew = og * tanhf(creg);

        if (t < S_SEQ - 1) {
            g_hbuf[(t + 1) & 1][b * NH + j] = hnew;
            __threadfence();
            __syncthreads();                 // all CTA stores done before arrive
            if (tid == 0) {
                atomicAdd(&g_bar[t], 1u);
                volatile unsigned* flag = &g_bar[t];
                while (*flag < (unsigned)NCTA) { }
            }
            __syncthreads();                 // release whole CTA
        } else {
            out[b * NH + j]           = hnew;   // h_T
            out[NB * NH + b * NH + j] = creg;   // c_T
        }
    }
}

// -------------------------------------------------------------------------
extern "C" void kernel_launch(void* const* d_in, const int* in_sizes, int n_in,
                              void* d_out, int out_size) {
    const float* x    = (const float*)d_in[0];
    const float* w_ii = (const float*)d_in[1];
    const float* b_ii = (const float*)d_in[2];
    const float* w_hi = (const float*)d_in[3];
    const float* b_hi = (const float*)d_in[4];
    const float* w_if = (const float*)d_in[5];
    const float* b_if = (const float*)d_in[6];
    const float* w_hf = (const float*)d_in[7];
    const float* b_hf = (const float*)d_in[8];
    const float* w_ig = (const float*)d_in[9];
    const float* b_ig = (const float*)d_in[10];
    const float* w_hg = (const float*)d_in[11];
    const float* b_hg = (const float*)d_in[12];
    const float* w_io = (const float*)d_in[13];
    const float* b_io = (const float*)d_in[14];
    const float* w_ho = (const float*)d_in[15];
    const float* b_ho = (const float*)d_in[16];

    cudaFuncSetAttribute(rec_kernel, cudaFuncAttributeMaxDynamicSharedMemorySize,
                         REC_SMEM_BYTES);

    // 1) zero the per-step barrier counters (stream-ordered before the scan)
    reset_kernel<<<8, 256>>>();

    // 2) input projections (all timesteps, 4 gates, biases folded)
    ProjPtrs p;
    p.w[0] = w_ii; p.w[1] = w_if; p.w[2] = w_ig; p.w[3] = w_io;
    p.bx[0] = b_ii; p.bx[1] = b_if; p.bx[2] = b_ig; p.bx[3] = b_io;
    p.bh[0] = b_hi; p.bh[1] = b_hf; p.bh[2] = b_hg; p.bh[3] = b_ho;
    proj_kernel<<<dim3(16, 1024), 256>>>(x, p);

    // 3) persistent sequential scan
    rec_kernel<<<NCTA, REC_THREADS, REC_SMEM_BYTES>>>(w_hi, w_hf, w_hg, w_ho,
                                                      (float*)d_out);
}

// round 2
// speedup vs baseline: 1.1038x; 1.1038x over previous
#include <cuda_runtime.h>
#include <math.h>

#define S_SEQ 2048
#define NB 64
#define NH 512
#define NF 512
#define NGATE 4
#define NCTA 128
#define REC_THREADS 256

// Scratch: pre-activations xpre[s][gate][b][h]  (1.07 GB), h ping-pong, barriers.
__device__ float    g_xpre[(size_t)S_SEQ * NGATE * NB * NH];
__device__ float    g_hbuf[2][NB * NH];
__device__ unsigned g_bar[S_SEQ];

// -------------------------------------------------------------------------
// Barrier-counter reset
// -------------------------------------------------------------------------
__global__ void reset_kernel() {
    int i = blockIdx.x * blockDim.x + threadIdx.x;
    if (i < S_SEQ) g_bar[i] = 0u;
}

// -------------------------------------------------------------------------
// tf32 helpers
// -------------------------------------------------------------------------
__device__ __forceinline__ float to_tf32(float f) {
    float r;
    asm("cvt.rna.tf32.f32 %0, %1;" : "=f"(r) : "f"(f));
    return r;
}

__device__ __forceinline__ void mma_tf32(float4& c, const float* a, const float* b) {
    asm volatile(
        "mma.sync.aligned.m16n8k8.row.col.f32.tf32.tf32.f32 "
        "{%0,%1,%2,%3}, {%4,%5,%6,%7}, {%8,%9}, {%0,%1,%2,%3};"
        : "+f"(c.x), "+f"(c.y), "+f"(c.z), "+f"(c.w)
        : "r"(__float_as_uint(a[0])), "r"(__float_as_uint(a[1])),
          "r"(__float_as_uint(a[2])), "r"(__float_as_uint(a[3])),
          "r"(__float_as_uint(b[0])), "r"(__float_as_uint(b[1])));
}

// -------------------------------------------------------------------------
// Input projection on tensor cores (tf32 mma.sync, fp32 accumulate).
//   C[r, n] = x[r, :] @ W_g[:, h] + bx[g][h] + bh[g][h]
//   r = b*2048 + s, n = g*512 + h.
// CTA tile 128x128, BK=32, 256 threads = 8 warps (warp grid 2m x 4n),
// warp tile 64x32 built from m16n8k8 atoms.
// Smem padded: As stride 36 (36%32==4 -> bank = 4*row+col, conflict-free
// for the a-fragment pattern), Bs stride 136 (136%32==8 -> bank = 8*row+col).
// -------------------------------------------------------------------------
struct ProjPtrs {
    const float* w[4];
    const float* bx[4];
    const float* bh[4];
};

__global__ __launch_bounds__(256, 2)
void proj_tf32_kernel(const float* __restrict__ x, ProjPtrs p) {
    __shared__ float As[128][36];   // [row][k]   (tf32-converted)
    __shared__ float Bs[32][136];   // [k][col]   (tf32-converted)

    const int tid  = threadIdx.x;
    const int lane = tid & 31;
    const int wid  = tid >> 5;
    const int wm   = wid & 1;        // 0..1  (m warp)
    const int wn   = wid >> 1;       // 0..3  (n warp)
    const int gq   = lane >> 2;      // groupID 0..7
    const int tq   = lane & 3;       // threadID_in_group 0..3

    const int nTile = blockIdx.x;    // 0..15
    const int mTile = blockIdx.y;    // 0..1023
    const int r0    = mTile * 128;
    const int g     = nTile >> 2;
    const int hc0   = (nTile & 3) * 128;
    const float* W  = p.w[g];

    float4 ga[4], gb[4];

    // prologue gmem prefetch (k0 = 0)
#pragma unroll
    for (int i = 0; i < 4; ++i) {
        const int e  = tid + i * 256;
        const int ar = e >> 3, akq = e & 7;
        ga[i] = *reinterpret_cast<const float4*>(x + (size_t)(r0 + ar) * NF + akq * 4);
        const int br = e >> 5, bcq = e & 31;
        gb[i] = *reinterpret_cast<const float4*>(W + (size_t)br * NH + hc0 + bcq * 4);
    }

    float4 acc[4][4];
#pragma unroll
    for (int mt = 0; mt < 4; ++mt)
#pragma unroll
        for (int nt = 0; nt < 4; ++nt)
            acc[mt][nt] = make_float4(0.f, 0.f, 0.f, 0.f);

    for (int it = 0; it < NF / 32; ++it) {
        __syncthreads();
        // deposit tiles (convert to tf32 at store time)
#pragma unroll
        for (int i = 0; i < 4; ++i) {
            const int e  = tid + i * 256;
            const int ar = e >> 3, akq = e & 7;
            As[ar][akq * 4 + 0] = to_tf32(ga[i].x);
            As[ar][akq * 4 + 1] = to_tf32(ga[i].y);
            As[ar][akq * 4 + 2] = to_tf32(ga[i].z);
            As[ar][akq * 4 + 3] = to_tf32(ga[i].w);
            const int br = e >> 5, bcq = e & 31;
            Bs[br][bcq * 4 + 0] = to_tf32(gb[i].x);
            Bs[br][bcq * 4 + 1] = to_tf32(gb[i].y);
            Bs[br][bcq * 4 + 2] = to_tf32(gb[i].z);
            Bs[br][bcq * 4 + 3] = to_tf32(gb[i].w);
        }
        __syncthreads();

        // prefetch next k tile
        if (it + 1 < NF / 32) {
            const int k0 = (it + 1) * 32;
#pragma unroll
            for (int i = 0; i < 4; ++i) {
                const int e  = tid + i * 256;
                const int ar = e >> 3, akq = e & 7;
                ga[i] = *reinterpret_cast<const float4*>(
                    x + (size_t)(r0 + ar) * NF + k0 + akq * 4);
                const int br = e >> 5, bcq = e & 31;
                gb[i] = *reinterpret_cast<const float4*>(
                    W + (size_t)(k0 + br) * NH + hc0 + bcq * 4);
            }
        }

        // compute: 4 k8-chunks
#pragma unroll
        for (int kc = 0; kc < 4; ++kc) {
            const int kb = kc * 8;
            float af[4][4];
            float bf[4][2];
#pragma unroll
            for (int mt = 0; mt < 4; ++mt) {
                const int rb = wm * 64 + mt * 16 + gq;
                af[mt][0] = As[rb][kb + tq];
                af[mt][1] = As[rb + 8][kb + tq];
                af[mt][2] = As[rb][kb + tq + 4];
                af[mt][3] = As[rb + 8][kb + tq + 4];
            }
#pragma unroll
            for (int nt = 0; nt < 4; ++nt) {
                const int cb = wn * 32 + nt * 8 + gq;
                bf[nt][0] = Bs[kb + tq][cb];
                bf[nt][1] = Bs[kb + tq + 4][cb];
            }
#pragma unroll
            for (int mt = 0; mt < 4; ++mt)
#pragma unroll
                for (int nt = 0; nt < 4; ++nt)
                    mma_tf32(acc[mt][nt], af[mt], bf[nt]);
        }
    }

    // epilogue: bias add + store to g_xpre[s][g][b][h]
#pragma unroll
    for (int nt = 0; nt < 4; ++nt) {
        const int colb = hc0 + wn * 32 + nt * 8 + tq * 2;  // h index within gate
        const float bias0 = p.bx[g][colb]     + p.bh[g][colb];
        const float bias1 = p.bx[g][colb + 1] + p.bh[g][colb + 1];
#pragma unroll
        for (int mt = 0; mt < 4; ++mt) {
            const int r1 = r0 + wm * 64 + mt * 16 + gq;
            const int r2 = r1 + 8;
            {
                const int bb = r1 >> 11, s = r1 & 2047;
                const size_t base = ((size_t)(s * 4 + g) * NB + bb) * NH;
                float2 v = make_float2(acc[mt][nt].x + bias0, acc[mt][nt].y + bias1);
                *reinterpret_cast<float2*>(&g_xpre[base + colb]) = v;
            }
            {
                const int bb = r2 >> 11, s = r2 & 2047;
                const size_t base = ((size_t)(s * 4 + g) * NB + bb) * NH;
                float2 v = make_float2(acc[mt][nt].z + bias0, acc[mt][nt].w + bias1);
                *reinterpret_cast<float2*>(&g_xpre[base + colb]) = v;
            }
        }
    }
}

// -------------------------------------------------------------------------
// Persistent recurrent kernel (unchanged from Round 1): 128 CTAs, each owns
// 4 hidden columns; W_h slice in smem; h broadcast via L2 each step; global
// barrier per step on pre-zeroed counters.
// -------------------------------------------------------------------------
#define WS_FLOATS (512 * 16)
#define HS_STRIDE 516
#define HS_FLOATS (NB * HS_STRIDE)
#define XS_FLOATS (NGATE * NB * 4)
#define REC_SMEM_BYTES ((WS_FLOATS + HS_FLOATS + XS_FLOATS) * 4)

__device__ __forceinline__ float sigmoidf_(float v) {
    return 1.f / (1.f + expf(-v));
}

__global__ __launch_bounds__(REC_THREADS, 1)
void rec_kernel(const float* __restrict__ w_hi, const float* __restrict__ w_hf,
                const float* __restrict__ w_hg, const float* __restrict__ w_ho,
                float* __restrict__ out) {
    extern __shared__ float sm[];
    float* w_s = sm;                       // [k*16 + jj*4 + g]
    float* h_s = sm + WS_FLOATS;           // [b*516 + k]
    float* x_s = h_s + HS_FLOATS;          // [(g*64+b)*4 + jj]

    const int tid = threadIdx.x;
    const int b   = tid & 63;
    const int jj  = tid >> 6;
    const int j0  = blockIdx.x * 4;
    const int j   = j0 + jj;

    {
        const float* wh[4] = {w_hi, w_hf, w_hg, w_ho};
        for (int idx = tid; idx < WS_FLOATS; idx += REC_THREADS) {
            const int k  = idx >> 4;
            const int jw = (idx >> 2) & 3;
            const int gw = idx & 3;
            w_s[idx] = wh[gw][(size_t)k * NH + j0 + jw];
        }
    }

    const float4* ws4  = reinterpret_cast<const float4*>(w_s) + jj;
    float4*       hs4w = reinterpret_cast<float4*>(h_s);
    const int gl = tid >> 6;
    const int bl = tid & 63;

    float creg = 0.f;

    for (int t = 0; t < S_SEQ; ++t) {
        const float4 xv = *reinterpret_cast<const float4*>(
            &g_xpre[(((size_t)t * 4 + gl) * NB + bl) * NH + j0]);

        if (t > 0) {
            const float4* hsrc = reinterpret_cast<const float4*>(g_hbuf[t & 1]);
#pragma unroll 4
            for (int i = tid; i < (NB * NH / 4); i += REC_THREADS) {
                float4 v = __ldcg(hsrc + i);
                const int bb = i >> 7;
                const int k4 = i & 127;
                hs4w[bb * (HS_STRIDE / 4) + k4] = v;
            }
        }
        *reinterpret_cast<float4*>(&x_s[(gl * NB + bl) * 4]) = xv;
        __syncthreads();

        float a0 = x_s[(0 * NB + b) * 4 + jj];
        float a1 = x_s[(1 * NB + b) * 4 + jj];
        float a2 = x_s[(2 * NB + b) * 4 + jj];
        float a3 = x_s[(3 * NB + b) * 4 + jj];

        if (t > 0) {
            const float4* hrow = reinterpret_cast<const float4*>(h_s) + b * (HS_STRIDE / 4);
#pragma unroll 2
            for (int k4 = 0; k4 < NH / 4; ++k4) {
                const float4 h4 = hrow[k4];
                const float4 w0 = ws4[k4 * 16 + 0];
                a0 += h4.x * w0.x; a1 += h4.x * w0.y; a2 += h4.x * w0.z; a3 += h4.x * w0.w;
                const float4 w1 = ws4[k4 * 16 + 4];
                a0 += h4.y * w1.x; a1 += h4.y * w1.y; a2 += h4.y * w1.z; a3 += h4.y * w1.w;
                const float4 w2 = ws4[k4 * 16 + 8];
                a0 += h4.z * w2.x; a1 += h4.z * w2.y; a2 += h4.z * w2.z; a3 += h4.z * w2.w;
                const float4 w3 = ws4[k4 * 16 + 12];
                a0 += h4.w * w3.x; a1 += h4.w * w3.y; a2 += h4.w * w3.z; a3 += h4.w * w3.w;
            }
        }

        const float ig = sigmoidf_(a0);
        const float fg = sigmoidf_(a1);
        const float gg = tanhf(a2);
        const float og = sigmoidf_(a3);
        creg = fg * creg + ig * gg;
        const float hnew = og * tanhf(creg);

        if (t < S_SEQ - 1) {
            g_hbuf[(t + 1) & 1][b * NH + j] = hnew;
            __threadfence();
            __syncthreads();
            if (tid == 0) {
                atomicAdd(&g_bar[t], 1u);
                volatile unsigned* flag = &g_bar[t];
                while (*flag < (unsigned)NCTA) { }
            }
            __syncthreads();
        } else {
            out[b * NH + j]           = hnew;
            out[NB * NH + b * NH + j] = creg;
        }
    }
}

// -------------------------------------------------------------------------
extern "C" void kernel_launch(void* const* d_in, const int* in_sizes, int n_in,
                              void* d_out, int out_size) {
    const float* x    = (const float*)d_in[0];
    const float* w_ii = (const float*)d_in[1];
    const float* b_ii = (const float*)d_in[2];
    const float* w_hi = (const float*)d_in[3];
    const float* b_hi = (const float*)d_in[4];
    const float* w_if = (const float*)d_in[5];
    const float* b_if = (const float*)d_in[6];
    const float* w_hf = (const float*)d_in[7];
    const float* b_hf = (const float*)d_in[8];
    const float* w_ig = (const float*)d_in[9];
    const float* b_ig = (const float*)d_in[10];
    const float* w_hg = (const float*)d_in[11];
    const float* b_hg = (const float*)d_in[12];
    const float* w_io = (const float*)d_in[13];
    const float* b_io = (const float*)d_in[14];
    const float* w_ho = (const float*)d_in[15];
    const float* b_ho = (const float*)d_in[16];

    cudaFuncSetAttribute(rec_kernel, cudaFuncAttributeMaxDynamicSharedMemorySize,
                         REC_SMEM_BYTES);

    reset_kernel<<<8, 256>>>();

    ProjPtrs p;
    p.w[0] = w_ii; p.w[1] = w_if; p.w[2] = w_ig; p.w[3] = w_io;
    p.bx[0] = b_ii; p.bx[1] = b_if; p.bx[2] = b_ig; p.bx[3] = b_io;
    p.bh[0] = b_hi; p.bh[1] = b_hf; p.bh[2] = b_hg; p.bh[3] = b_ho;
    proj_tf32_kernel<<<dim3(16, 1024), 256>>>(x, p);

    rec_kernel<<<NCTA, REC_THREADS, REC_SMEM_BYTES>>>(w_hi, w_hf, w_hg, w_ho,
                                                      (float*)d_out);
}

// round 3
// speedup vs baseline: 1.9117x; 1.7319x over previous
#include <cuda_runtime.h>
#include <math.h>

#define S_SEQ 2048
#define NB 64
#define NH 512
#define NF 512
#define NGATE 4
#define REC_THREADS 256
#define NCTA_REC 64

// Scratch: pre-activations xpre[s][gate][b][h] (1.07 GB), h ping-pong, barriers.
__device__ float    g_xpre[(size_t)S_SEQ * NGATE * NB * NH];
__device__ float    g_hbuf[2][NB * NH];
__device__ unsigned g_bar[S_SEQ];

// -------------------------------------------------------------------------
__global__ void reset_kernel() {
    int i = blockIdx.x * blockDim.x + threadIdx.x;
    if (i < S_SEQ) g_bar[i] = 0u;
}

// -------------------------------------------------------------------------
// tf32 helpers
// -------------------------------------------------------------------------
__device__ __forceinline__ float to_tf32(float f) {
    float r;
    asm("cvt.rna.tf32.f32 %0, %1;" : "=f"(r) : "f"(f));
    return r;
}

__device__ __forceinline__ void mma_tf32(float4& c, const float* a, const float* b) {
    asm volatile(
        "mma.sync.aligned.m16n8k8.row.col.f32.tf32.tf32.f32 "
        "{%0,%1,%2,%3}, {%4,%5,%6,%7}, {%8,%9}, {%0,%1,%2,%3};"
        : "+f"(c.x), "+f"(c.y), "+f"(c.z), "+f"(c.w)
        : "r"(__float_as_uint(a[0])), "r"(__float_as_uint(a[1])),
          "r"(__float_as_uint(a[2])), "r"(__float_as_uint(a[3])),
          "r"(__float_as_uint(b[0])), "r"(__float_as_uint(b[1])));
}

// -------------------------------------------------------------------------
// Input projection on tensor cores (unchanged from Round 2).
// -------------------------------------------------------------------------
struct ProjPtrs {
    const float* w[4];
    const float* bx[4];
    const float* bh[4];
};

__global__ __launch_bounds__(256, 2)
void proj_tf32_kernel(const float* __restrict__ x, ProjPtrs p) {
    __shared__ float As[128][36];
    __shared__ float Bs[32][136];

    const int tid  = threadIdx.x;
    const int lane = tid & 31;
    const int wid  = tid >> 5;
    const int wm   = wid & 1;
    const int wn   = wid >> 1;
    const int gq   = lane >> 2;
    const int tq   = lane & 3;

    const int nTile = blockIdx.x;
    const int mTile = blockIdx.y;
    const int r0    = mTile * 128;
    const int g     = nTile >> 2;
    const int hc0   = (nTile & 3) * 128;
    const float* W  = p.w[g];

    float4 ga[4], gb[4];
#pragma unroll
    for (int i = 0; i < 4; ++i) {
        const int e  = tid + i * 256;
        const int ar = e >> 3, akq = e & 7;
        ga[i] = *reinterpret_cast<const float4*>(x + (size_t)(r0 + ar) * NF + akq * 4);
        const int br = e >> 5, bcq = e & 31;
        gb[i] = *reinterpret_cast<const float4*>(W + (size_t)br * NH + hc0 + bcq * 4);
    }

    float4 acc[4][4];
#pragma unroll
    for (int mt = 0; mt < 4; ++mt)
#pragma unroll
        for (int nt = 0; nt < 4; ++nt)
            acc[mt][nt] = make_float4(0.f, 0.f, 0.f, 0.f);

    for (int it = 0; it < NF / 32; ++it) {
        __syncthreads();
#pragma unroll
        for (int i = 0; i < 4; ++i) {
            const int e  = tid + i * 256;
            const int ar = e >> 3, akq = e & 7;
            As[ar][akq * 4 + 0] = to_tf32(ga[i].x);
            As[ar][akq * 4 + 1] = to_tf32(ga[i].y);
            As[ar][akq * 4 + 2] = to_tf32(ga[i].z);
            As[ar][akq * 4 + 3] = to_tf32(ga[i].w);
            const int br = e >> 5, bcq = e & 31;
            Bs[br][bcq * 4 + 0] = to_tf32(gb[i].x);
            Bs[br][bcq * 4 + 1] = to_tf32(gb[i].y);
            Bs[br][bcq * 4 + 2] = to_tf32(gb[i].z);
            Bs[br][bcq * 4 + 3] = to_tf32(gb[i].w);
        }
        __syncthreads();

        if (it + 1 < NF / 32) {
            const int k0 = (it + 1) * 32;
#pragma unroll
            for (int i = 0; i < 4; ++i) {
                const int e  = tid + i * 256;
                const int ar = e >> 3, akq = e & 7;
                ga[i] = *reinterpret_cast<const float4*>(
                    x + (size_t)(r0 + ar) * NF + k0 + akq * 4);
                const int br = e >> 5, bcq = e & 31;
                gb[i] = *reinterpret_cast<const float4*>(
                    W + (size_t)(k0 + br) * NH + hc0 + bcq * 4);
            }
        }

#pragma unroll
        for (int kc = 0; kc < 4; ++kc) {
            const int kb = kc * 8;
            float af[4][4];
            float bf[4][2];
#pragma unroll
            for (int mt = 0; mt < 4; ++mt) {
                const int rb = wm * 64 + mt * 16 + gq;
                af[mt][0] = As[rb][kb + tq];
                af[mt][1] = As[rb + 8][kb + tq];
                af[mt][2] = As[rb][kb + tq + 4];
                af[mt][3] = As[rb + 8][kb + tq + 4];
            }
#pragma unroll
            for (int nt = 0; nt < 4; ++nt) {
                const int cb = wn * 32 + nt * 8 + gq;
                bf[nt][0] = Bs[kb + tq][cb];
                bf[nt][1] = Bs[kb + tq + 4][cb];
            }
#pragma unroll
            for (int mt = 0; mt < 4; ++mt)
#pragma unroll
                for (int nt = 0; nt < 4; ++nt)
                    mma_tf32(acc[mt][nt], af[mt], bf[nt]);
        }
    }

#pragma unroll
    for (int nt = 0; nt < 4; ++nt) {
        const int colb = hc0 + wn * 32 + nt * 8 + tq * 2;
        const float bias0 = p.bx[g][colb]     + p.bh[g][colb];
        const float bias1 = p.bx[g][colb + 1] + p.bh[g][colb + 1];
#pragma unroll
        for (int mt = 0; mt < 4; ++mt) {
            const int r1 = r0 + wm * 64 + mt * 16 + gq;
            const int r2 = r1 + 8;
            {
                const int bb = r1 >> 11, s = r1 & 2047;
                const size_t base = ((size_t)(s * 4 + g) * NB + bb) * NH;
                float2 v = make_float2(acc[mt][nt].x + bias0, acc[mt][nt].y + bias1);
                *reinterpret_cast<float2*>(&g_xpre[base + colb]) = v;
            }
            {
                const int bb = r2 >> 11, s = r2 & 2047;
                const size_t base = ((size_t)(s * 4 + g) * NB + bb) * NH;
                float2 v = make_float2(acc[mt][nt].z + bias0, acc[mt][nt].w + bias1);
                *reinterpret_cast<float2*>(&g_xpre[base + colb]) = v;
            }
        }
    }
}

// -------------------------------------------------------------------------
// Tensor-core recurrent kernel.
// 64 CTAs x 256 threads. CTA c owns h-columns [c*8, c*8+8) x 4 gates
// (n = jj*4 + g, 32 output cols), all 64 batches.
// W_h fragments live in REGISTERS (loaded once). k is split across 8 warps
// (64-wide slice each); partials reduced through smem.
// h ping-pong buffer holds tf32-rounded h (only ever feeds the mma).
// -------------------------------------------------------------------------
#define HS_STRIDE 516                       // floats; 516 % 32 == 4 (conflict-free)
#define HS_FLOATS (NB * HS_STRIDE)          // 33024
#define RED_STRIDE 36
#define RED_FLOATS (8 * NB * RED_STRIDE)    // 18432
#define REC_SMEM_BYTES ((HS_FLOATS + RED_FLOATS) * 4)

__device__ __forceinline__ float sigmoidf_(float v) {
    return 1.f / (1.f + expf(-v));
}

__global__ __launch_bounds__(REC_THREADS, 1)
void rec_mma_kernel(const float* __restrict__ w_hi, const float* __restrict__ w_hf,
                    const float* __restrict__ w_hg, const float* __restrict__ w_ho,
                    float* __restrict__ out) {
    extern __shared__ float sm[];
    float* h_s = sm;                    // [b][k], stride 516
    float* red = sm + HS_FLOATS;        // [warp][row 64][col 32 pad 36]

    const int tid  = threadIdx.x;
    const int lane = tid & 31;
    const int wid  = tid >> 5;          // k-slice owner: k in [wid*64, wid*64+64)
    const int gq   = lane >> 2;         // 0..7
    const int tq   = lane & 3;          // 0..3
    const int j0   = blockIdx.x * 8;    // first h-column of this CTA

    // ---- load persistent W_h B-fragments into registers --------------------
    // n = nt*8 + gq ; jj = n>>2 ; g = n&3 ; col = j0 + jj
    // b[kc][nt][0] = W_g[kw*64 + kc*8 + tq ][col] ; [1] = row +4
    float breg[8][4][2];
    {
        const float* wh[4] = {w_hi, w_hf, w_hg, w_ho};
#pragma unroll
        for (int nt = 0; nt < 4; ++nt) {
            const int n  = nt * 8 + gq;
            const float* wp = wh[n & 3] + j0 + (n >> 2);
#pragma unroll
            for (int kc = 0; kc < 8; ++kc) {
                const int k0 = wid * 64 + kc * 8 + tq;
                breg[kc][nt][0] = to_tf32(wp[(size_t)k0 * NH]);
                breg[kc][nt][1] = to_tf32(wp[(size_t)(k0 + 4) * NH]);
            }
        }
    }

    // ---- per-thread epilogue ownership -------------------------------------
    // thread t owns (b = t>>2, j = j0 + (t&3)*2 .. +1): 2 h columns.
    const int eb   = tid >> 2;
    const int ejj  = (tid & 3) * 2;
    const int ej   = j0 + ejj;
    float c0 = 0.f, c1 = 0.f;

    float4* hs4 = reinterpret_cast<float4*>(h_s);

    for (int t = 0; t < S_SEQ; ++t) {
        float sums[8];
#pragma unroll
        for (int i = 0; i < 8; ++i) sums[i] = 0.f;

        if (t > 0) {
            // ---- stage h_t (already tf32-rounded) into smem -----------------
            const float4* hsrc = reinterpret_cast<const float4*>(g_hbuf[t & 1]);
#pragma unroll
            for (int i = tid; i < (NB * NH / 4); i += REC_THREADS) {
                float4 v = __ldcg(hsrc + i);
                hs4[(i >> 7) * (HS_STRIDE / 4) + (i & 127)] = v;
            }
            __syncthreads();

            // ---- mma over this warp's k-slice -------------------------------
            float4 acc[4][4];
#pragma unroll
            for (int mt = 0; mt < 4; ++mt)
#pragma unroll
                for (int nt = 0; nt < 4; ++nt)
                    acc[mt][nt] = make_float4(0.f, 0.f, 0.f, 0.f);

#pragma unroll
            for (int kc = 0; kc < 8; ++kc) {
                const int kcol = wid * 64 + kc * 8 + tq;
                float af[4][4];
#pragma unroll
                for (int mt = 0; mt < 4; ++mt) {
                    const int row = mt * 16 + gq;
                    af[mt][0] = h_s[row * HS_STRIDE + kcol];
                    af[mt][1] = h_s[(row + 8) * HS_STRIDE + kcol];
                    af[mt][2] = h_s[row * HS_STRIDE + kcol + 4];
                    af[mt][3] = h_s[(row + 8) * HS_STRIDE + kcol + 4];
                }
#pragma unroll
                for (int mt = 0; mt < 4; ++mt)
#pragma unroll
                    for (int nt = 0; nt < 4; ++nt)
                        mma_tf32(acc[mt][nt], af[mt], breg[kc][nt]);
            }

            // ---- dump partials ----------------------------------------------
            // C[row][col]: row = mt*16+gq(+8), col = nt*8 + tq*2 (+1)
            float* rw = red + wid * (NB * RED_STRIDE);
#pragma unroll
            for (int mt = 0; mt < 4; ++mt)
#pragma unroll
                for (int nt = 0; nt < 4; ++nt) {
                    const int row = mt * 16 + gq;
                    const int col = nt * 8 + tq * 2;
                    *reinterpret_cast<float2*>(&rw[row * RED_STRIDE + col]) =
                        make_float2(acc[mt][nt].x, acc[mt][nt].y);
                    *reinterpret_cast<float2*>(&rw[(row + 8) * RED_STRIDE + col]) =
                        make_float2(acc[mt][nt].z, acc[mt][nt].w);
                }
            __syncthreads();

            // ---- reduce 8 warp-partials for this thread's 8 cols ------------
            const int cb = ejj * 4;                 // = (tid&3)*8
#pragma unroll
            for (int w = 0; w < 8; ++w) {
                const float* rp = red + (w * NB + eb) * RED_STRIDE + cb;
                float4 v0 = *reinterpret_cast<const float4*>(rp);
                float4 v1 = *reinterpret_cast<const float4*>(rp + 4);
                sums[0] += v0.x; sums[1] += v0.y; sums[2] += v0.z; sums[3] += v0.w;
                sums[4] += v1.x; sums[5] += v1.y; sums[6] += v1.z; sums[7] += v1.w;
            }
        }

        // ---- epilogue: x pre-acts + activations + state update --------------
        float pre0[4], pre1[4];
#pragma unroll
        for (int g = 0; g < 4; ++g) {
            const float2 xv = *reinterpret_cast<const float2*>(
                &g_xpre[(((size_t)t * 4 + g) * NB + eb) * NH + ej]);
            pre0[g] = sums[g]     + xv.x;
            pre1[g] = sums[4 + g] + xv.y;
        }

        const float i0 = sigmoidf_(pre0[0]), i1 = sigmoidf_(pre1[0]);
        const float f0 = sigmoidf_(pre0[1]), f1 = sigmoidf_(pre1[1]);
        const float g0 = tanhf(pre0[2]),     g1 = tanhf(pre1[2]);
        const float o0 = sigmoidf_(pre0[3]), o1 = sigmoidf_(pre1[3]);
        c0 = f0 * c0 + i0 * g0;
        c1 = f1 * c1 + i1 * g1;
        const float h0 = o0 * tanhf(c0);
        const float h1 = o1 * tanhf(c1);

        if (t < S_SEQ - 1) {
            *reinterpret_cast<float2*>(&g_hbuf[(t + 1) & 1][eb * NH + ej]) =
                make_float2(to_tf32(h0), to_tf32(h1));
            __threadfence();
            __syncthreads();
            if (tid == 0) {
                atomicAdd(&g_bar[t], 1u);
                volatile unsigned* flag = &g_bar[t];
                while (*flag < (unsigned)NCTA_REC) { }
            }
            __syncthreads();
        } else {
            out[eb * NH + ej]               = h0;
            out[eb * NH + ej + 1]           = h1;
            out[NB * NH + eb * NH + ej]     = c0;
            out[NB * NH + eb * NH + ej + 1] = c1;
        }
    }
}

// -------------------------------------------------------------------------
extern "C" void kernel_launch(void* const* d_in, const int* in_sizes, int n_in,
                              void* d_out, int out_size) {
    const float* x    = (const float*)d_in[0];
    const float* w_ii = (const float*)d_in[1];
    const float* b_ii = (const float*)d_in[2];
    const float* w_hi = (const float*)d_in[3];
    const float* b_hi = (const float*)d_in[4];
    const float* w_if = (const float*)d_in[5];
    const float* b_if = (const float*)d_in[6];
    const float* w_hf = (const float*)d_in[7];
    const float* b_hf = (const float*)d_in[8];
    const float* w_ig = (const float*)d_in[9];
    const float* b_ig = (const float*)d_in[10];
    const float* w_hg = (const float*)d_in[11];
    const float* b_hg = (const float*)d_in[12];
    const float* w_io = (const float*)d_in[13];
    const float* b_io = (const float*)d_in[14];
    const float* w_ho = (const float*)d_in[15];
    const float* b_ho = (const float*)d_in[16];

    cudaFuncSetAttribute(rec_mma_kernel, cudaFuncAttributeMaxDynamicSharedMemorySize,
                         REC_SMEM_BYTES);

    reset_kernel<<<8, 256>>>();

    ProjPtrs p;
    p.w[0] = w_ii; p.w[1] = w_if; p.w[2] = w_ig; p.w[3] = w_io;
    p.bx[0] = b_ii; p.bx[1] = b_if; p.bx[2] = b_ig; p.bx[3] = b_io;
    p.bh[0] = b_hi; p.bh[1] = b_hf; p.bh[2] = b_hg; p.bh[3] = b_ho;
    proj_tf32_kernel<<<dim3(16, 1024), 256>>>(x, p);

    rec_mma_kernel<<<NCTA_REC, REC_THREADS, REC_SMEM_BYTES>>>(
        w_hi, w_hf, w_hg, w_ho, (float*)d_out);
}

// round 4
// speedup vs baseline: 2.3696x; 1.2395x over previous
#include <cuda_runtime.h>
#include <math.h>

#define S_SEQ 2048
#define NB 64
#define NH 512
#define NF 512
#define NGATE 4
#define REC_THREADS 256
#define NCTA_REC 64
#define BAR_TARGET (NCTA_REC * 8)   // warp-granular arrivals

// Scratch: pre-activations xpre[s][gate][b][h] (1.07 GB), h ping-pong, barriers.
__device__ float    g_xpre[(size_t)S_SEQ * NGATE * NB * NH];
__device__ float    g_hbuf[2][NB * NH];
__device__ unsigned g_bar[S_SEQ];

// -------------------------------------------------------------------------
__global__ void reset_kernel() {
    int i = blockIdx.x * blockDim.x + threadIdx.x;
    if (i < S_SEQ) g_bar[i] = 0u;
}

// -------------------------------------------------------------------------
// tf32 helpers
// -------------------------------------------------------------------------
__device__ __forceinline__ float to_tf32(float f) {
    float r;
    asm("cvt.rna.tf32.f32 %0, %1;" : "=f"(r) : "f"(f));
    return r;
}

__device__ __forceinline__ void mma_tf32(float4& c, const float* a, const float* b) {
    asm volatile(
        "mma.sync.aligned.m16n8k8.row.col.f32.tf32.tf32.f32 "
        "{%0,%1,%2,%3}, {%4,%5,%6,%7}, {%8,%9}, {%0,%1,%2,%3};"
        : "+f"(c.x), "+f"(c.y), "+f"(c.z), "+f"(c.w)
        : "r"(__float_as_uint(a[0])), "r"(__float_as_uint(a[1])),
          "r"(__float_as_uint(a[2])), "r"(__float_as_uint(a[3])),
          "r"(__float_as_uint(b[0])), "r"(__float_as_uint(b[1])));
}

// -------------------------------------------------------------------------
// Input projection on tensor cores (unchanged from Round 2/3).
// -------------------------------------------------------------------------
struct ProjPtrs {
    const float* w[4];
    const float* bx[4];
    const float* bh[4];
};

__global__ __launch_bounds__(256, 2)
void proj_tf32_kernel(const float* __restrict__ x, ProjPtrs p) {
    __shared__ float As[128][36];
    __shared__ float Bs[32][136];

    const int tid  = threadIdx.x;
    const int lane = tid & 31;
    const int wid  = tid >> 5;
    const int wm   = wid & 1;
    const int wn   = wid >> 1;
    const int gq   = lane >> 2;
    const int tq   = lane & 3;

    const int nTile = blockIdx.x;
    const int mTile = blockIdx.y;
    const int r0    = mTile * 128;
    const int g     = nTile >> 2;
    const int hc0   = (nTile & 3) * 128;
    const float* W  = p.w[g];

    float4 ga[4], gb[4];
#pragma unroll
    for (int i = 0; i < 4; ++i) {
        const int e  = tid + i * 256;
        const int ar = e >> 3, akq = e & 7;
        ga[i] = *reinterpret_cast<const float4*>(x + (size_t)(r0 + ar) * NF + akq * 4);
        const int br = e >> 5, bcq = e & 31;
        gb[i] = *reinterpret_cast<const float4*>(W + (size_t)br * NH + hc0 + bcq * 4);
    }

    float4 acc[4][4];
#pragma unroll
    for (int mt = 0; mt < 4; ++mt)
#pragma unroll
        for (int nt = 0; nt < 4; ++nt)
            acc[mt][nt] = make_float4(0.f, 0.f, 0.f, 0.f);

    for (int it = 0; it < NF / 32; ++it) {
        __syncthreads();
#pragma unroll
        for (int i = 0; i < 4; ++i) {
            const int e  = tid + i * 256;
            const int ar = e >> 3, akq = e & 7;
            As[ar][akq * 4 + 0] = to_tf32(ga[i].x);
            As[ar][akq * 4 + 1] = to_tf32(ga[i].y);
            As[ar][akq * 4 + 2] = to_tf32(ga[i].z);
            As[ar][akq * 4 + 3] = to_tf32(ga[i].w);
            const int br = e >> 5, bcq = e & 31;
            Bs[br][bcq * 4 + 0] = to_tf32(gb[i].x);
            Bs[br][bcq * 4 + 1] = to_tf32(gb[i].y);
            Bs[br][bcq * 4 + 2] = to_tf32(gb[i].z);
            Bs[br][bcq * 4 + 3] = to_tf32(gb[i].w);
        }
        __syncthreads();

        if (it + 1 < NF / 32) {
            const int k0 = (it + 1) * 32;
#pragma unroll
            for (int i = 0; i < 4; ++i) {
                const int e  = tid + i * 256;
                const int ar = e >> 3, akq = e & 7;
                ga[i] = *reinterpret_cast<const float4*>(
                    x + (size_t)(r0 + ar) * NF + k0 + akq * 4);
                const int br = e >> 5, bcq = e & 31;
                gb[i] = *reinterpret_cast<const float4*>(
                    W + (size_t)(k0 + br) * NH + hc0 + bcq * 4);
            }
        }

#pragma unroll
        for (int kc = 0; kc < 4; ++kc) {
            const int kb = kc * 8;
            float af[4][4];
            float bf[4][2];
#pragma unroll
            for (int mt = 0; mt < 4; ++mt) {
                const int rb = wm * 64 + mt * 16 + gq;
                af[mt][0] = As[rb][kb + tq];
                af[mt][1] = As[rb + 8][kb + tq];
                af[mt][2] = As[rb][kb + tq + 4];
                af[mt][3] = As[rb + 8][kb + tq + 4];
            }
#pragma unroll
            for (int nt = 0; nt < 4; ++nt) {
                const int cb = wn * 32 + nt * 8 + gq;
                bf[nt][0] = Bs[kb + tq][cb];
                bf[nt][1] = Bs[kb + tq + 4][cb];
            }
#pragma unroll
            for (int mt = 0; mt < 4; ++mt)
#pragma unroll
                for (int nt = 0; nt < 4; ++nt)
                    mma_tf32(acc[mt][nt], af[mt], bf[nt]);
        }
    }

#pragma unroll
    for (int nt = 0; nt < 4; ++nt) {
        const int colb = hc0 + wn * 32 + nt * 8 + tq * 2;
        const float bias0 = p.bx[g][colb]     + p.bh[g][colb];
        const float bias1 = p.bx[g][colb + 1] + p.bh[g][colb + 1];
#pragma unroll
        for (int mt = 0; mt < 4; ++mt) {
            const int r1 = r0 + wm * 64 + mt * 16 + gq;
            const int r2 = r1 + 8;
            {
                const int bb = r1 >> 11, s = r1 & 2047;
                const size_t base = ((size_t)(s * 4 + g) * NB + bb) * NH;
                float2 v = make_float2(acc[mt][nt].x + bias0, acc[mt][nt].y + bias1);
                *reinterpret_cast<float2*>(&g_xpre[base + colb]) = v;
            }
            {
                const int bb = r2 >> 11, s = r2 & 2047;
                const size_t base = ((size_t)(s * 4 + g) * NB + bb) * NH;
                float2 v = make_float2(acc[mt][nt].z + bias0, acc[mt][nt].w + bias1);
                *reinterpret_cast<float2*>(&g_xpre[base + colb]) = v;
            }
        }
    }
}

// -------------------------------------------------------------------------
// Tensor-core recurrent kernel, pipeline-decoupled.
// 64 CTAs x 256 threads (8 warps). CTA owns 8 h-cols x 4 gates (32 outputs).
// Warp w owns k-slice [w*64, w*64+64): stages ONLY its slice into private
// smem, so no CTA sync between barrier-wait/stage/mma. W_h fragments live in
// registers. Global barrier counts WARP arrivals (512) with release/acquire
// atomics (no threadfence, no CTA-wide arrive sync).
// -------------------------------------------------------------------------
#define SLICE_STRIDE 68                         // 68 % 32 == 4 -> conflict-free
#define SLICE_FLOATS (NB * SLICE_STRIDE)        // 4352 per warp
#define RED_STRIDE 36
#define RED_FLOATS (8 * NB * RED_STRIDE)        // 18432
#define REC_SMEM_BYTES ((8 * SLICE_FLOATS + RED_FLOATS) * 4)   // 212992 B

__device__ __forceinline__ float fsig(float v) {
    return __fdividef(1.f, 1.f + __expf(-v));
}
__device__ __forceinline__ float ftanh(float v) {
    return 1.f - __fdividef(2.f, __expf(2.f * v) + 1.f);
}

__global__ __launch_bounds__(REC_THREADS, 1)
void rec_mma_kernel(const float* __restrict__ w_hi, const float* __restrict__ w_hf,
                    const float* __restrict__ w_hg, const float* __restrict__ w_ho,
                    float* __restrict__ out) {
    extern __shared__ float sm[];
    float* red = sm + 8 * SLICE_FLOATS;     // [warp][row 64][col 32 pad 36]

    const int tid  = threadIdx.x;
    const int lane = tid & 31;
    const int wid  = tid >> 5;
    const int gq   = lane >> 2;
    const int tq   = lane & 3;
    const int j0   = blockIdx.x * 8;

    float* slice = sm + wid * SLICE_FLOATS; // this warp's h k-slice

    // ---- persistent W_h B-fragments in registers ---------------------------
    float breg[8][4][2];
    {
        const float* wh[4] = {w_hi, w_hf, w_hg, w_ho};
#pragma unroll
        for (int nt = 0; nt < 4; ++nt) {
            const int n  = nt * 8 + gq;
            const float* wp = wh[n & 3] + j0 + (n >> 2);
#pragma unroll
            for (int kc = 0; kc < 8; ++kc) {
                const int k0 = wid * 64 + kc * 8 + tq;
                breg[kc][nt][0] = to_tf32(wp[(size_t)k0 * NH]);
                breg[kc][nt][1] = to_tf32(wp[(size_t)(k0 + 4) * NH]);
            }
        }
    }

    // epilogue ownership: thread t -> (b = t>>2, cols ej, ej+1)
    const int eb  = tid >> 2;
    const int ejj = (tid & 3) * 2;
    const int ej  = j0 + ejj;
    float c0 = 0.f, c1 = 0.f;

    for (int t = 0; t < S_SEQ; ++t) {
        // ---- prefetch x_t (consumed in epilogue; hidden behind spin/mma) ----
        float2 xv[4];
#pragma unroll
        for (int g = 0; g < 4; ++g)
            xv[g] = __ldcg(reinterpret_cast<const float2*>(
                &g_xpre[(((size_t)t * 4 + g) * NB + eb) * NH + ej]));

        if (t > 0) {
            // ---- warp-level acquire spin on previous step's barrier ---------
            unsigned v;
            do {
                asm volatile("ld.acquire.gpu.global.u32 %0, [%1];"
                             : "=r"(v) : "l"(g_bar + (t - 1)) : "memory");
            } while (v < (unsigned)BAR_TARGET);

            // ---- stage this warp's k-slice of h_t ----------------------------
            const float4* hsrc4 = reinterpret_cast<const float4*>(g_hbuf[t & 1]);
#pragma unroll 8
            for (int it = 0; it < 32; ++it) {
                const int i   = it * 32 + lane;   // 0..1023
                const int row = i >> 4;
                const int c4  = i & 15;
                float4 hv = __ldcg(hsrc4 + (size_t)row * (NH / 4) + wid * 16 + c4);
                *reinterpret_cast<float4*>(&slice[row * SLICE_STRIDE + c4 * 4]) = hv;
            }
            __syncwarp();

            // ---- mma over own k-slice ---------------------------------------
            float4 acc[4][4];
#pragma unroll
            for (int mt = 0; mt < 4; ++mt)
#pragma unroll
                for (int nt = 0; nt < 4; ++nt)
                    acc[mt][nt] = make_float4(0.f, 0.f, 0.f, 0.f);

#pragma unroll
            for (int kc = 0; kc < 8; ++kc) {
                const int kcol = kc * 8 + tq;     // local col within slice
                float af[4][4];
#pragma unroll
                for (int mt = 0; mt < 4; ++mt) {
                    const int row = mt * 16 + gq;
                    af[mt][0] = slice[row * SLICE_STRIDE + kcol];
                    af[mt][1] = slice[(row + 8) * SLICE_STRIDE + kcol];
                    af[mt][2] = slice[row * SLICE_STRIDE + kcol + 4];
                    af[mt][3] = slice[(row + 8) * SLICE_STRIDE + kcol + 4];
                }
#pragma unroll
                for (int mt = 0; mt < 4; ++mt)
#pragma unroll
                    for (int nt = 0; nt < 4; ++nt)
                        mma_tf32(acc[mt][nt], af[mt], breg[kc][nt]);
            }

            // ---- dump partials -----------------------------------------------
            float* rw = red + wid * (NB * RED_STRIDE);
#pragma unroll
            for (int mt = 0; mt < 4; ++mt)
#pragma unroll
                for (int nt = 0; nt < 4; ++nt) {
                    const int row = mt * 16 + gq;
                    const int col = nt * 8 + tq * 2;
                    *reinterpret_cast<float2*>(&rw[row * RED_STRIDE + col]) =
                        make_float2(acc[mt][nt].x, acc[mt][nt].y);
                    *reinterpret_cast<float2*>(&rw[(row + 8) * RED_STRIDE + col]) =
                        make_float2(acc[mt][nt].z, acc[mt][nt].w);
                }
        }
        __syncthreads();

        // ---- reduce 8 warp-partials + epilogue -------------------------------
        float sums[8];
#pragma unroll
        for (int i = 0; i < 8; ++i) sums[i] = 0.f;
        if (t > 0) {
            const int cb = ejj * 4;
#pragma unroll
            for (int w = 0; w < 8; ++w) {
                const float* rp = red + (w * NB + eb) * RED_STRIDE + cb;
                float4 v0 = *reinterpret_cast<const float4*>(rp);
                float4 v1 = *reinterpret_cast<const float4*>(rp + 4);
                sums[0] += v0.x; sums[1] += v0.y; sums[2] += v0.z; sums[3] += v0.w;
                sums[4] += v1.x; sums[5] += v1.y; sums[6] += v1.z; sums[7] += v1.w;
            }
        }

        const float i0 = fsig(sums[0] + xv[0].x), i1 = fsig(sums[4] + xv[0].y);
        const float f0 = fsig(sums[1] + xv[1].x), f1 = fsig(sums[5] + xv[1].y);
        const float g0 = ftanh(sums[2] + xv[2].x), g1 = ftanh(sums[6] + xv[2].y);
        const float o0 = fsig(sums[3] + xv[3].x), o1 = fsig(sums[7] + xv[3].y);
        c0 = f0 * c0 + i0 * g0;
        c1 = f1 * c1 + i1 * g1;
        const float h0 = o0 * ftanh(c0);
        const float h1 = o1 * ftanh(c1);

        if (t < S_SEQ - 1) {
            *reinterpret_cast<float2*>(&g_hbuf[(t + 1) & 1][eb * NH + ej]) =
                make_float2(to_tf32(h0), to_tf32(h1));
            __syncwarp();
            if (lane == 0) {
                asm volatile("red.release.gpu.global.add.u32 [%0], %1;"
                             :: "l"(g_bar + t), "r"(1u) : "memory");
            }
        } else {
            out[eb * NH + ej]               = h0;
            out[eb * NH + ej + 1]           = h1;
            out[NB * NH + eb * NH + ej]     = c0;
            out[NB * NH + eb * NH + ej + 1] = c1;
        }
    }
}

// -------------------------------------------------------------------------
extern "C" void kernel_launch(void* const* d_in, const int* in_sizes, int n_in,
                              void* d_out, int out_size) {
    const float* x    = (const float*)d_in[0];
    const float* w_ii = (const float*)d_in[1];
    const float* b_ii = (const float*)d_in[2];
    const float* w_hi = (const float*)d_in[3];
    const float* b_hi = (const float*)d_in[4];
    const float* w_if = (const float*)d_in[5];
    const float* b_if = (const float*)d_in[6];
    const float* w_hf = (const float*)d_in[7];
    const float* b_hf = (const float*)d_in[8];
    const float* w_ig = (const float*)d_in[9];
    const float* b_ig = (const float*)d_in[10];
    const float* w_hg = (const float*)d_in[11];
    const float* b_hg = (const float*)d_in[12];
    const float* w_io = (const float*)d_in[13];
    const float* b_io = (const float*)d_in[14];
    const float* w_ho = (const float*)d_in[15];
    const float* b_ho = (const float*)d_in[16];

    cudaFuncSetAttribute(rec_mma_kernel, cudaFuncAttributeMaxDynamicSharedMemorySize,
                         REC_SMEM_BYTES);

    reset_kernel<<<8, 256>>>();

    ProjPtrs p;
    p.w[0] = w_ii; p.w[1] = w_if; p.w[2] = w_ig; p.w[3] = w_io;
    p.bx[0] = b_ii; p.bx[1] = b_if; p.bx[2] = b_ig; p.bx[3] = b_io;
    p.bh[0] = b_hi; p.bh[1] = b_hf; p.bh[2] = b_hg; p.bh[3] = b_ho;
    proj_tf32_kernel<<<dim3(16, 1024), 256>>>(x, p);

    rec_mma_kernel<<<NCTA_REC, REC_THREADS, REC_SMEM_BYTES>>>(
        w_hi, w_hf, w_hg, w_ho, (float*)d_out);
}

// round 5
// speedup vs baseline: 3.8385x; 1.6199x over previous
#include <cuda_runtime.h>
#include <math.h>

#define S_SEQ 2048
#define NB 64
#define NH 512
#define NF 512
#define NGATE 4
#define REC_THREADS 256

#define NGROUP 4                 // batch groups (16 batches each)
#define GB 16                    // batches per group
#define CTA_PER_GROUP 32         // 32 CTAs x 16 h-cols = 2048 n-cols
#define NCTA_REC (NGROUP * CTA_PER_GROUP)     // 128
#define BAR_TARGET (CTA_PER_GROUP * 8)        // 256 warp arrivals per group

// Scratch: pre-activations xpre[s][gate][b][h] (1.07 GB), h ping-pong, barriers.
__device__ float    g_xpre[(size_t)S_SEQ * NGATE * NB * NH];
__device__ float    g_hbuf[2][NB * NH];
__device__ unsigned g_bar[NGROUP * S_SEQ];

// -------------------------------------------------------------------------
__global__ void reset_kernel() {
    int i = blockIdx.x * blockDim.x + threadIdx.x;
    if (i < NGROUP * S_SEQ) g_bar[i] = 0u;
}

// -------------------------------------------------------------------------
// tf32 helpers
// -------------------------------------------------------------------------
__device__ __forceinline__ float to_tf32(float f) {
    float r;
    asm("cvt.rna.tf32.f32 %0, %1;" : "=f"(r) : "f"(f));
    return r;
}

__device__ __forceinline__ void mma_tf32(float4& c, const float* a, const float* b) {
    asm volatile(
        "mma.sync.aligned.m16n8k8.row.col.f32.tf32.tf32.f32 "
        "{%0,%1,%2,%3}, {%4,%5,%6,%7}, {%8,%9}, {%0,%1,%2,%3};"
        : "+f"(c.x), "+f"(c.y), "+f"(c.z), "+f"(c.w)
        : "r"(__float_as_uint(a[0])), "r"(__float_as_uint(a[1])),
          "r"(__float_as_uint(a[2])), "r"(__float_as_uint(a[3])),
          "r"(__float_as_uint(b[0])), "r"(__float_as_uint(b[1])));
}

// -------------------------------------------------------------------------
// Input projection on tensor cores (unchanged since Round 2).
// -------------------------------------------------------------------------
struct ProjPtrs {
    const float* w[4];
    const float* bx[4];
    const float* bh[4];
};

__global__ __launch_bounds__(256, 2)
void proj_tf32_kernel(const float* __restrict__ x, ProjPtrs p) {
    __shared__ float As[128][36];
    __shared__ float Bs[32][136];

    const int tid  = threadIdx.x;
    const int lane = tid & 31;
    const int wid  = tid >> 5;
    const int wm   = wid & 1;
    const int wn   = wid >> 1;
    const int gq   = lane >> 2;
    const int tq   = lane & 3;

    const int nTile = blockIdx.x;
    const int mTile = blockIdx.y;
    const int r0    = mTile * 128;
    const int g     = nTile >> 2;
    const int hc0   = (nTile & 3) * 128;
    const float* W  = p.w[g];

    float4 ga[4], gb[4];
#pragma unroll
    for (int i = 0; i < 4; ++i) {
        const int e  = tid + i * 256;
        const int ar = e >> 3, akq = e & 7;
        ga[i] = *reinterpret_cast<const float4*>(x + (size_t)(r0 + ar) * NF + akq * 4);
        const int br = e >> 5, bcq = e & 31;
        gb[i] = *reinterpret_cast<const float4*>(W + (size_t)br * NH + hc0 + bcq * 4);
    }

    float4 acc[4][4];
#pragma unroll
    for (int mt = 0; mt < 4; ++mt)
#pragma unroll
        for (int nt = 0; nt < 4; ++nt)
            acc[mt][nt] = make_float4(0.f, 0.f, 0.f, 0.f);

    for (int it = 0; it < NF / 32; ++it) {
        __syncthreads();
#pragma unroll
        for (int i = 0; i < 4; ++i) {
            const int e  = tid + i * 256;
            const int ar = e >> 3, akq = e & 7;
            As[ar][akq * 4 + 0] = to_tf32(ga[i].x);
            As[ar][akq * 4 + 1] = to_tf32(ga[i].y);
            As[ar][akq * 4 + 2] = to_tf32(ga[i].z);
            As[ar][akq * 4 + 3] = to_tf32(ga[i].w);
            const int br = e >> 5, bcq = e & 31;
            Bs[br][bcq * 4 + 0] = to_tf32(gb[i].x);
            Bs[br][bcq * 4 + 1] = to_tf32(gb[i].y);
            Bs[br][bcq * 4 + 2] = to_tf32(gb[i].z);
            Bs[br][bcq * 4 + 3] = to_tf32(gb[i].w);
        }
        __syncthreads();

        if (it + 1 < NF / 32) {
            const int k0 = (it + 1) * 32;
#pragma unroll
            for (int i = 0; i < 4; ++i) {
                const int e  = tid + i * 256;
                const int ar = e >> 3, akq = e & 7;
                ga[i] = *reinterpret_cast<const float4*>(
                    x + (size_t)(r0 + ar) * NF + k0 + akq * 4);
                const int br = e >> 5, bcq = e & 31;
                gb[i] = *reinterpret_cast<const float4*>(
                    W + (size_t)(k0 + br) * NH + hc0 + bcq * 4);
            }
        }

#pragma unroll
        for (int kc = 0; kc < 4; ++kc) {
            const int kb = kc * 8;
            float af[4][4];
            float bf[4][2];
#pragma unroll
            for (int mt = 0; mt < 4; ++mt) {
                const int rb = wm * 64 + mt * 16 + gq;
                af[mt][0] = As[rb][kb + tq];
                af[mt][1] = As[rb + 8][kb + tq];
                af[mt][2] = As[rb][kb + tq + 4];
                af[mt][3] = As[rb + 8][kb + tq + 4];
            }
#pragma unroll
            for (int nt = 0; nt < 4; ++nt) {
                const int cb = wn * 32 + nt * 8 + gq;
                bf[nt][0] = Bs[kb + tq][cb];
                bf[nt][1] = Bs[kb + tq + 4][cb];
            }
#pragma unroll
            for (int mt = 0; mt < 4; ++mt)
#pragma unroll
                for (int nt = 0; nt < 4; ++nt)
                    mma_tf32(acc[mt][nt], af[mt], bf[nt]);
        }
    }

#pragma unroll
    for (int nt = 0; nt < 4; ++nt) {
        const int colb = hc0 + wn * 32 + nt * 8 + tq * 2;
        const float bias0 = p.bx[g][colb]     + p.bh[g][colb];
        const float bias1 = p.bx[g][colb + 1] + p.bh[g][colb + 1];
#pragma unroll
        for (int mt = 0; mt < 4; ++mt) {
            const int r1 = r0 + wm * 64 + mt * 16 + gq;
            const int r2 = r1 + 8;
            {
                const int bb = r1 >> 11, s = r1 & 2047;
                const size_t base = ((size_t)(s * 4 + g) * NB + bb) * NH;
                float2 v = make_float2(acc[mt][nt].x + bias0, acc[mt][nt].y + bias1);
                *reinterpret_cast<float2*>(&g_xpre[base + colb]) = v;
            }
            {
                const int bb = r2 >> 11, s = r2 & 2047;
                const size_t base = ((size_t)(s * 4 + g) * NB + bb) * NH;
                float2 v = make_float2(acc[mt][nt].z + bias0, acc[mt][nt].w + bias1);
                *reinterpret_cast<float2*>(&g_xpre[base + colb]) = v;
            }
        }
    }
}

// -------------------------------------------------------------------------
// Tensor-core recurrent kernel, batch-partitioned.
// 128 CTAs = 4 batch-groups x 32 CTAs. Group owns 16 batches; CTA owns
// 16 h-cols x 4 gates (64 n-cols). Warp w owns k-slice [w*64, w*64+64):
// stages 16x64 of h (8 independent LDG.128/thread), mma m16 (mt=1) x nt=8
// x kc=8 with register-resident W_h fragments; per-group warp-granular
// release/acquire barrier.
// -------------------------------------------------------------------------
#define SLICE_STRIDE 68                          // 68 % 32 == 4 -> conflict-free
#define SLICE_FLOATS (GB * SLICE_STRIDE)         // 1088 per warp
#define RED_STRIDE 68
#define RED_FLOATS (8 * GB * RED_STRIDE)         // 8704
#define REC_SMEM_BYTES ((8 * SLICE_FLOATS + RED_FLOATS) * 4)   // 69632 B

__device__ __forceinline__ float fsig(float v) {
    return __fdividef(1.f, 1.f + __expf(-v));
}
__device__ __forceinline__ float ftanh(float v) {
    return 1.f - __fdividef(2.f, __expf(2.f * v) + 1.f);
}

__global__ __launch_bounds__(REC_THREADS, 1)
void rec_mma_kernel(const float* __restrict__ w_hi, const float* __restrict__ w_hf,
                    const float* __restrict__ w_hg, const float* __restrict__ w_ho,
                    float* __restrict__ out) {
    extern __shared__ float sm[];
    float* red = sm + 8 * SLICE_FLOATS;     // [warp][row 16][col 64 pad 68]

    const int tid   = threadIdx.x;
    const int lane  = tid & 31;
    const int wid   = tid >> 5;
    const int gq    = lane >> 2;
    const int tq    = lane & 3;
    const int group = blockIdx.x >> 5;      // 0..3
    const int cidx  = blockIdx.x & 31;      // 0..31
    const int c0    = cidx * 16;            // first h-col of this CTA
    unsigned* bar   = g_bar + group * S_SEQ;

    float* slice = sm + wid * SLICE_FLOATS;

    // ---- persistent W_h B-fragments in registers ---------------------------
    // n = nt*8 + gq (0..63); jj = n>>2; g = n&3; col = c0 + jj
    float breg[8][8][2];
    {
        const float* wh[4] = {w_hi, w_hf, w_hg, w_ho};
#pragma unroll
        for (int nt = 0; nt < 8; ++nt) {
            const int n  = nt * 8 + gq;
            const float* wp = wh[n & 3] + c0 + (n >> 2);
#pragma unroll
            for (int kc = 0; kc < 8; ++kc) {
                const int k0 = wid * 64 + kc * 8 + tq;
                breg[kc][nt][0] = to_tf32(wp[(size_t)k0 * NH]);
                breg[kc][nt][1] = to_tf32(wp[(size_t)(k0 + 4) * NH]);
            }
        }
    }

    // epilogue ownership: thread <-> (b = tid>>4 in group, jj = tid&15)
    const int eb  = tid >> 4;               // 0..15 (local batch)
    const int ejj = tid & 15;               // 0..15 (local h-col)
    const int gb  = group * GB + eb;        // global batch
    const int ej  = c0 + ejj;               // global h-col
    float cst = 0.f;

    for (int t = 0; t < S_SEQ; ++t) {
        // ---- prefetch x_t (4 gates, consumed in epilogue) --------------------
        float xv[4];
#pragma unroll
        for (int g = 0; g < 4; ++g)
            xv[g] = __ldcg(&g_xpre[(((size_t)t * 4 + g) * NB + gb) * NH + ej]);

        if (t > 0) {
            // ---- warp-level acquire spin on this group's previous barrier ----
            unsigned v;
            do {
                asm volatile("ld.acquire.gpu.global.u32 %0, [%1];"
                             : "=r"(v) : "l"(bar + (t - 1)) : "memory");
            } while (v < (unsigned)BAR_TARGET);

            // ---- stage this warp's 16 x 64 h-slice (8 independent LDG.128) ---
            const float* hsrc = g_hbuf[t & 1];
#pragma unroll
            for (int it = 0; it < 8; ++it) {
                const int i   = it * 32 + lane;   // 0..255
                const int row = i >> 4;           // 0..15
                const int c4  = i & 15;           // 0..15
                float4 hv = __ldcg(reinterpret_cast<const float4*>(
                    hsrc + (size_t)(group * GB + row) * NH + wid * 64 + c4 * 4));
                *reinterpret_cast<float4*>(&slice[row * SLICE_STRIDE + c4 * 4]) = hv;
            }
            __syncwarp();

            // ---- mma m16 x n64 over own k-slice -------------------------------
            float4 acc[8];
#pragma unroll
            for (int nt = 0; nt < 8; ++nt) acc[nt] = make_float4(0.f, 0.f, 0.f, 0.f);

#pragma unroll
            for (int kc = 0; kc < 8; ++kc) {
                const int kcol = kc * 8 + tq;
                float af[4];
                af[0] = slice[gq * SLICE_STRIDE + kcol];
                af[1] = slice[(gq + 8) * SLICE_STRIDE + kcol];
                af[2] = slice[gq * SLICE_STRIDE + kcol + 4];
                af[3] = slice[(gq + 8) * SLICE_STRIDE + kcol + 4];
#pragma unroll
                for (int nt = 0; nt < 8; ++nt)
                    mma_tf32(acc[nt], af, breg[kc][nt]);
            }

            // ---- dump partials ------------------------------------------------
            float* rw = red + wid * (GB * RED_STRIDE);
#pragma unroll
            for (int nt = 0; nt < 8; ++nt) {
                const int col = nt * 8 + tq * 2;
                *reinterpret_cast<float2*>(&rw[gq * RED_STRIDE + col]) =
                    make_float2(acc[nt].x, acc[nt].y);
                *reinterpret_cast<float2*>(&rw[(gq + 8) * RED_STRIDE + col]) =
                    make_float2(acc[nt].z, acc[nt].w);
            }
        }
        __syncthreads();

        // ---- reduce 8 warp-partials (one LDS.128 each) + epilogue ------------
        float s0 = 0.f, s1 = 0.f, s2 = 0.f, s3 = 0.f;
        if (t > 0) {
#pragma unroll
            for (int w = 0; w < 8; ++w) {
                const float4 v = *reinterpret_cast<const float4*>(
                    &red[(w * GB + eb) * RED_STRIDE + ejj * 4]);
                s0 += v.x; s1 += v.y; s2 += v.z; s3 += v.w;
            }
        }

        const float ig = fsig(s0 + xv[0]);
        const float fg = fsig(s1 + xv[1]);
        const float gg = ftanh(s2 + xv[2]);
        const float og = fsig(s3 + xv[3]);
        cst = fg * cst + ig * gg;
        const float hnew = og * ftanh(cst);

        if (t < S_SEQ - 1) {
            g_hbuf[(t + 1) & 1][gb * NH + ej] = to_tf32(hnew);
            __syncwarp();
            if (lane == 0) {
                asm volatile("red.release.gpu.global.add.u32 [%0], %1;"
                             :: "l"(bar + t), "r"(1u) : "memory");
            }
        } else {
            out[gb * NH + ej]           = hnew;
            out[NB * NH + gb * NH + ej] = cst;
        }
    }
}

// -------------------------------------------------------------------------
extern "C" void kernel_launch(void* const* d_in, const int* in_sizes, int n_in,
                              void* d_out, int out_size) {
    const float* x    = (const float*)d_in[0];
    const float* w_ii = (const float*)d_in[1];
    const float* b_ii = (const float*)d_in[2];
    const float* w_hi = (const float*)d_in[3];
    const float* b_hi = (const float*)d_in[4];
    const float* w_if = (const float*)d_in[5];
    const float* b_if = (const float*)d_in[6];
    const float* w_hf = (const float*)d_in[7];
    const float* b_hf = (const float*)d_in[8];
    const float* w_ig = (const float*)d_in[9];
    const float* b_ig = (const float*)d_in[10];
    const float* w_hg = (const float*)d_in[11];
    const float* b_hg = (const float*)d_in[12];
    const float* w_io = (const float*)d_in[13];
    const float* b_io = (const float*)d_in[14];
    const float* w_ho = (const float*)d_in[15];
    const float* b_ho = (const float*)d_in[16];

    cudaFuncSetAttribute(rec_mma_kernel, cudaFuncAttributeMaxDynamicSharedMemorySize,
                         REC_SMEM_BYTES);

    reset_kernel<<<32, 256>>>();

    ProjPtrs p;
    p.w[0] = w_ii; p.w[1] = w_if; p.w[2] = w_ig; p.w[3] = w_io;
    p.bx[0] = b_ii; p.bx[1] = b_if; p.bx[2] = b_ig; p.bx[3] = b_io;
    p.bh[0] = b_hi; p.bh[1] = b_hf; p.bh[2] = b_hg; p.bh[3] = b_ho;
    proj_tf32_kernel<<<dim3(16, 1024), 256>>>(x, p);

    rec_mma_kernel<<<NCTA_REC, REC_THREADS, REC_SMEM_BYTES>>>(
        w_hi, w_hf, w_hg, w_ho, (float*)d_out);
}

// round 6
// speedup vs baseline: 3.9852x; 1.0382x over previous
#include <cuda_runtime.h>
#include <math.h>

#define S_SEQ 2048
#define NB 64
#define NH 512
#define NF 512
#define NGATE 4
#define REC_THREADS 256

#define NGROUP 4                 // batch groups (16 batches each)
#define GB 16                    // batches per group
#define CTA_PER_GROUP 32         // 32 CTAs x 16 h-cols = 2048 n-cols
#define NCTA_REC (NGROUP * CTA_PER_GROUP)     // 128
#define BAR_TARGET (CTA_PER_GROUP * 8)        // 256 warp arrivals per group

// Scratch: pre-activations xpre[s][gate][b][h] (1.07 GB), h ping-pong, barriers.
__device__ float    g_xpre[(size_t)S_SEQ * NGATE * NB * NH];
__device__ float    g_hbuf[2][NB * NH];
__device__ unsigned g_bar[NGROUP * S_SEQ];   // zero-init; self-cleaning (see rec)

// -------------------------------------------------------------------------
// tf32 helpers
// -------------------------------------------------------------------------
__device__ __forceinline__ float to_tf32(float f) {
    float r;
    asm("cvt.rna.tf32.f32 %0, %1;" : "=f"(r) : "f"(f));
    return r;
}

__device__ __forceinline__ void mma_tf32(float4& c, const float* a, const float* b) {
    asm volatile(
        "mma.sync.aligned.m16n8k8.row.col.f32.tf32.tf32.f32 "
        "{%0,%1,%2,%3}, {%4,%5,%6,%7}, {%8,%9}, {%0,%1,%2,%3};"
        : "+f"(c.x), "+f"(c.y), "+f"(c.z), "+f"(c.w)
        : "r"(__float_as_uint(a[0])), "r"(__float_as_uint(a[1])),
          "r"(__float_as_uint(a[2])), "r"(__float_as_uint(a[3])),
          "r"(__float_as_uint(b[0])), "r"(__float_as_uint(b[1])));
}

// -------------------------------------------------------------------------
// Input projection v2: 128 threads = 4 warps, warp tile 64x64 (wm 0..1 x
// wn 0..1), CTA tile 128x128, BK=32, double-buffered dynamic smem,
// fragment-order A layout (one LDS.128 per (mt,kc) a-fragment).
// -------------------------------------------------------------------------
struct ProjPtrs {
    const float* w[4];
    const float* bx[4];
    const float* bh[4];
};

#define PROJ_THREADS 128
#define AF_FLOATS 4224            // 32 regions x 132 (pad 4 -> 2-way STS only)
#define BS_FLOATS 4352            // 32 x 136
#define PBUF_FLOATS (AF_FLOATS + BS_FLOATS)
#define PROJ_SMEM_BYTES (2 * PBUF_FLOATS * 4)   // 68608 B

__global__ __launch_bounds__(PROJ_THREADS, 2)
void proj_tf32_kernel(const float* __restrict__ x, ProjPtrs p) {
    extern __shared__ float psm[];

    const int tid  = threadIdx.x;
    const int lane = tid & 31;
    const int wid  = tid >> 5;        // 0..3
    const int wm   = wid & 1;
    const int wn   = wid >> 1;
    const int gq   = lane >> 2;
    const int tq   = lane & 3;

    const int nTile = blockIdx.x;     // 0..15
    const int mTile = blockIdx.y;     // 0..1023
    const int r0    = mTile * 128;
    const int g     = nTile >> 2;
    const int hc0   = (nTile & 3) * 128;
    const float* W  = p.w[g];

    float4 ga[8], gb[8];

    // ---- gmem load of one BK=32 tile into registers ------------------------
    auto load_tile = [&](int k0) {
#pragma unroll
        for (int i = 0; i < 8; ++i) {
            const int e  = tid + i * PROJ_THREADS;       // 0..1023
            const int ar = e >> 3, akq = e & 7;
            ga[i] = *reinterpret_cast<const float4*>(
                x + (size_t)(r0 + ar) * NF + k0 + akq * 4);
            const int br = e >> 5, bcq = e & 31;
            gb[i] = *reinterpret_cast<const float4*>(
                W + (size_t)(k0 + br) * NH + hc0 + bcq * 4);
        }
    };

    // ---- deposit registers into buffer (fragment-order A, row-order B) -----
    auto stage_tile = [&](int buf) {
        float* A_f = psm + buf * PBUF_FLOATS;
        float* B_s = A_f + AF_FLOATS;
#pragma unroll
        for (int i = 0; i < 8; ++i) {
            const int e   = tid + i * PROJ_THREADS;
            const int ar  = e >> 3, akq = e & 7;
            const int wmS = ar >> 6;
            const int r6  = ar & 63;
            const int mtS = r6 >> 4;
            const int half = (r6 >> 3) & 1;
            const int gqS  = r6 & 7;
            const int kcS  = akq >> 1;
            const int quad = 2 * (akq & 1) + half;
            const int base = ((wmS * 4 + mtS) * 4 + kcS) * 132 + gqS * 16 + quad;
            A_f[base + 0]  = to_tf32(ga[i].x);
            A_f[base + 4]  = to_tf32(ga[i].y);
            A_f[base + 8]  = to_tf32(ga[i].z);
            A_f[base + 12] = to_tf32(ga[i].w);

            const int br = e >> 5, bcq = e & 31;
            B_s[br * 136 + bcq * 4 + 0] = to_tf32(gb[i].x);
            B_s[br * 136 + bcq * 4 + 1] = to_tf32(gb[i].y);
            B_s[br * 136 + bcq * 4 + 2] = to_tf32(gb[i].z);
            B_s[br * 136 + bcq * 4 + 3] = to_tf32(gb[i].w);
        }
    };

    float4 acc[4][8];
#pragma unroll
    for (int mt = 0; mt < 4; ++mt)
#pragma unroll
        for (int nt = 0; nt < 8; ++nt)
            acc[mt][nt] = make_float4(0.f, 0.f, 0.f, 0.f);

    load_tile(0);
    stage_tile(0);

    for (int it = 0; it < NF / 32; ++it) {
        __syncthreads();
        if (it + 1 < NF / 32) load_tile((it + 1) * 32);

        // ---- compute from buf[it&1] ----------------------------------------
        const float* A_f = psm + (it & 1) * PBUF_FLOATS;
        const float* B_s = A_f + AF_FLOATS;
#pragma unroll
        for (int kc = 0; kc < 4; ++kc) {
            float4 afv[4];
#pragma unroll
            for (int mt = 0; mt < 4; ++mt)
                afv[mt] = *reinterpret_cast<const float4*>(
                    &A_f[((wm * 4 + mt) * 4 + kc) * 132 + lane * 4]);
            float bf[8][2];
            const int kb = kc * 8;
#pragma unroll
            for (int nt = 0; nt < 8; ++nt) {
                const int cb = wn * 64 + nt * 8 + gq;
                bf[nt][0] = B_s[(kb + tq) * 136 + cb];
                bf[nt][1] = B_s[(kb + tq + 4) * 136 + cb];
            }
#pragma unroll
            for (int mt = 0; mt < 4; ++mt)
#pragma unroll
                for (int nt = 0; nt < 8; ++nt)
                    mma_tf32(acc[mt][nt], reinterpret_cast<float*>(&afv[mt]), bf[nt]);
        }

        if (it + 1 < NF / 32) stage_tile((it + 1) & 1);
    }

    // ---- epilogue: bias add + store to g_xpre[s][g][b][h] -------------------
#pragma unroll
    for (int nt = 0; nt < 8; ++nt) {
        const int colb = hc0 + wn * 64 + nt * 8 + tq * 2;
        const float bias0 = p.bx[g][colb]     + p.bh[g][colb];
        const float bias1 = p.bx[g][colb + 1] + p.bh[g][colb + 1];
#pragma unroll
        for (int mt = 0; mt < 4; ++mt) {
            const int r1 = r0 + wm * 64 + mt * 16 + gq;
            const int r2 = r1 + 8;
            {
                const int bb = r1 >> 11, s = r1 & 2047;
                const size_t base = ((size_t)(s * 4 + g) * NB + bb) * NH;
                *reinterpret_cast<float2*>(&g_xpre[base + colb]) =
                    make_float2(acc[mt][nt].x + bias0, acc[mt][nt].y + bias1);
            }
            {
                const int bb = r2 >> 11, s = r2 & 2047;
                const size_t base = ((size_t)(s * 4 + g) * NB + bb) * NH;
                *reinterpret_cast<float2*>(&g_xpre[base + colb]) =
                    make_float2(acc[mt][nt].z + bias0, acc[mt][nt].w + bias1);
            }
        }
    }
}

// -------------------------------------------------------------------------
// Tensor-core recurrent kernel (structure unchanged from Round 5) with
// SELF-CLEANING barriers: designated thread of each group resets slot t-2
// after passing wait(t-1) (all warps provably past it); one extra arrival
// on slot S_SEQ-1 at the end lets it zero the last two slots, so the
// barrier array returns to all-zero for the next graph replay.
// -------------------------------------------------------------------------
#define SLICE_STRIDE 68
#define SLICE_FLOATS (GB * SLICE_STRIDE)         // 1088 per warp
#define RED_STRIDE 68
#define RED_FLOATS (8 * GB * RED_STRIDE)         // 8704
#define REC_SMEM_BYTES ((8 * SLICE_FLOATS + RED_FLOATS) * 4)   // 69632 B

__device__ __forceinline__ float fsig(float v) {
    return __fdividef(1.f, 1.f + __expf(-v));
}
__device__ __forceinline__ float ftanh(float v) {
    return 1.f - __fdividef(2.f, __expf(2.f * v) + 1.f);
}

__global__ __launch_bounds__(REC_THREADS, 1)
void rec_mma_kernel(const float* __restrict__ w_hi, const float* __restrict__ w_hf,
                    const float* __restrict__ w_hg, const float* __restrict__ w_ho,
                    float* __restrict__ out) {
    extern __shared__ float sm[];
    float* red = sm + 8 * SLICE_FLOATS;

    const int tid   = threadIdx.x;
    const int lane  = tid & 31;
    const int wid   = tid >> 5;
    const int gq    = lane >> 2;
    const int tq    = lane & 3;
    const int group = blockIdx.x >> 5;
    const int cidx  = blockIdx.x & 31;
    const int c0    = cidx * 16;
    unsigned* bar   = g_bar + group * S_SEQ;
    const bool janitor = (cidx == 0 && tid == 0);

    float* slice = sm + wid * SLICE_FLOATS;

    // ---- persistent W_h B-fragments in registers ---------------------------
    float breg[8][8][2];
    {
        const float* wh[4] = {w_hi, w_hf, w_hg, w_ho};
#pragma unroll
        for (int nt = 0; nt < 8; ++nt) {
            const int n  = nt * 8 + gq;
            const float* wp = wh[n & 3] + c0 + (n >> 2);
#pragma unroll
            for (int kc = 0; kc < 8; ++kc) {
                const int k0 = wid * 64 + kc * 8 + tq;
                breg[kc][nt][0] = to_tf32(wp[(size_t)k0 * NH]);
                breg[kc][nt][1] = to_tf32(wp[(size_t)(k0 + 4) * NH]);
            }
        }
    }

    const int eb  = tid >> 4;
    const int ejj = tid & 15;
    const int gb  = group * GB + eb;
    const int ej  = c0 + ejj;
    float cst = 0.f;

    for (int t = 0; t < S_SEQ; ++t) {
        float xv[4];
#pragma unroll
        for (int g = 0; g < 4; ++g)
            xv[g] = __ldcg(&g_xpre[(((size_t)t * 4 + g) * NB + gb) * NH + ej]);

        if (t > 0) {
            unsigned v;
            do {
                asm volatile("ld.acquire.gpu.global.u32 %0, [%1];"
                             : "=r"(v) : "l"(bar + (t - 1)) : "memory");
            } while (v < (unsigned)BAR_TARGET);

            // self-clean: all warps provably past wait(t-2) now
            if (janitor && t >= 2)
                asm volatile("st.relaxed.gpu.global.u32 [%0], %1;"
                             :: "l"(bar + (t - 2)), "r"(0u) : "memory");

            const float* hsrc = g_hbuf[t & 1];
#pragma unroll
            for (int it = 0; it < 8; ++it) {
                const int i   = it * 32 + lane;
                const int row = i >> 4;
                const int c4  = i & 15;
                float4 hv = __ldcg(reinterpret_cast<const float4*>(
                    hsrc + (size_t)(group * GB + row) * NH + wid * 64 + c4 * 4));
                *reinterpret_cast<float4*>(&slice[row * SLICE_STRIDE + c4 * 4]) = hv;
            }
            __syncwarp();

            float4 acc[8];
#pragma unroll
            for (int nt = 0; nt < 8; ++nt) acc[nt] = make_float4(0.f, 0.f, 0.f, 0.f);

#pragma unroll
            for (int kc = 0; kc < 8; ++kc) {
                const int kcol = kc * 8 + tq;
                float af[4];
                af[0] = slice[gq * SLICE_STRIDE + kcol];
                af[1] = slice[(gq + 8) * SLICE_STRIDE + kcol];
                af[2] = slice[gq * SLICE_STRIDE + kcol + 4];
                af[3] = slice[(gq + 8) * SLICE_STRIDE + kcol + 4];
#pragma unroll
                for (int nt = 0; nt < 8; ++nt)
                    mma_tf32(acc[nt], af, breg[kc][nt]);
            }

            float* rw = red + wid * (GB * RED_STRIDE);
#pragma unroll
            for (int nt = 0; nt < 8; ++nt) {
                const int col = nt * 8 + tq * 2;
                *reinterpret_cast<float2*>(&rw[gq * RED_STRIDE + col]) =
                    make_float2(acc[nt].x, acc[nt].y);
                *reinterpret_cast<float2*>(&rw[(gq + 8) * RED_STRIDE + col]) =
                    make_float2(acc[nt].z, acc[nt].w);
            }
        }
        __syncthreads();

        float s0 = 0.f, s1 = 0.f, s2 = 0.f, s3 = 0.f;
        if (t > 0) {
#pragma unroll
            for (int w = 0; w < 8; ++w) {
                const float4 v = *reinterpret_cast<const float4*>(
                    &red[(w * GB + eb) * RED_STRIDE + ejj * 4]);
                s0 += v.x; s1 += v.y; s2 += v.z; s3 += v.w;
            }
        }

        const float ig = fsig(s0 + xv[0]);
        const float fg = fsig(s1 + xv[1]);
        const float gg = ftanh(s2 + xv[2]);
        const float og = fsig(s3 + xv[3]);
        cst = fg * cst + ig * gg;
        const float hnew = og * ftanh(cst);

        if (t < S_SEQ - 1) {
            g_hbuf[(t + 1) & 1][gb * NH + ej] = to_tf32(hnew);
            __syncwarp();
            if (lane == 0) {
                asm volatile("red.release.gpu.global.add.u32 [%0], %1;"
                             :: "l"(bar + t), "r"(1u) : "memory");
            }
        } else {
            out[gb * NH + ej]           = hnew;
            out[NB * NH + gb * NH + ej] = cst;
        }
    }

    // ---- final cleanup: extra arrival on unused slot S_SEQ-1, then zero ----
    __syncwarp();
    if (lane == 0)
        asm volatile("red.release.gpu.global.add.u32 [%0], %1;"
                     :: "l"(bar + (S_SEQ - 1)), "r"(1u) : "memory");
    if (janitor) {
        unsigned v;
        do {
            asm volatile("ld.acquire.gpu.global.u32 %0, [%1];"
                         : "=r"(v) : "l"(bar + (S_SEQ - 1)) : "memory");
        } while (v < (unsigned)BAR_TARGET);
        asm volatile("st.relaxed.gpu.global.u32 [%0], %1;"
                     :: "l"(bar + (S_SEQ - 2)), "r"(0u) : "memory");
        asm volatile("st.relaxed.gpu.global.u32 [%0], %1;"
                     :: "l"(bar + (S_SEQ - 1)), "r"(0u) : "memory");
    }
}

// -------------------------------------------------------------------------
extern "C" void kernel_launch(void* const* d_in, const int* in_sizes, int n_in,
                              void* d_out, int out_size) {
    const float* x    = (const float*)d_in[0];
    const float* w_ii = (const float*)d_in[1];
    const float* b_ii = (const float*)d_in[2];
    const float* w_hi = (const float*)d_in[3];
    const float* b_hi = (const float*)d_in[4];
    const float* w_if = (const float*)d_in[5];
    const float* b_if = (const float*)d_in[6];
    const float* w_hf = (const float*)d_in[7];
    const float* b_hf = (const float*)d_in[8];
    const float* w_ig = (const float*)d_in[9];
    const float* b_ig = (const float*)d_in[10];
    const float* w_hg = (const float*)d_in[11];
    const float* b_hg = (const float*)d_in[12];
    const float* w_io = (const float*)d_in[13];
    const float* b_io = (const float*)d_in[14];
    const float* w_ho = (const float*)d_in[15];
    const float* b_ho = (const float*)d_in[16];

    cudaFuncSetAttribute(proj_tf32_kernel, cudaFuncAttributeMaxDynamicSharedMemorySize,
                         PROJ_SMEM_BYTES);
    cudaFuncSetAttribute(rec_mma_kernel, cudaFuncAttributeMaxDynamicSharedMemorySize,
                         REC_SMEM_BYTES);

    ProjPtrs p;
    p.w[0] = w_ii; p.w[1] = w_if; p.w[2] = w_ig; p.w[3] = w_io;
    p.bx[0] = b_ii; p.bx[1] = b_if; p.bx[2] = b_ig; p.bx[3] = b_io;
    p.bh[0] = b_hi; p.bh[1] = b_hf; p.bh[2] = b_hg; p.bh[3] = b_ho;
    proj_tf32_kernel<<<dim3(16, 1024), PROJ_THREADS, PROJ_SMEM_BYTES>>>(x, p);

    rec_mma_kernel<<<NCTA_REC, REC_THREADS, REC_SMEM_BYTES>>>(
        w_hi, w_hf, w_hg, w_ho, (float*)d_out);
}